// round 11
// baseline (speedup 1.0000x reference)
#include <cuda_runtime.h>
#include <mma.h>
#include <math.h>

using namespace nvcuda;

#define SS 512
#define CC 384
#define HH 12
#define NPROJ 1152   // 192 qs + 192 ks + 192 vs + 144 qp + 144 kp + 288 vp
#define AD 32        // augmented logit dim (30 used, padded to 32)
#define VD 40        // 16 scalar + 8 points * 3
#define COMB 576     // 192 scalar_out + 288 pol + 96 norms

// ---------------- scratch (device globals; no allocation allowed) ----------
__device__ float g_Wh[CC * NPROJ];       // tf32-rounded hi part of packed W
__device__ float g_Wl[CC * NPROJ];       // tf32-rounded lo part
__device__ float g_Woh[COMB * CC];
__device__ float g_Wol[COMB * CC];
__device__ float g_bc[NPROJ];
__device__ float g_proj[SS * NPROJ];
__device__ float g_Qa[HH * AD * SS];     // dim-major augmented Q
__device__ float g_Ka[HH * AD * SS];     // dim-major augmented K
__device__ float g_Vc[HH * SS * VD];
__device__ float g_attn[HH * SS * SS];
__device__ float g_comb[SS * COMB];
__device__ float g_maskf[SS];
__device__ float g_spw[HH * 4];          // softplus(point_weights)

// ---------------- K0: pack + tf32-split weights, mask, softplus ------------
__global__ void pack_weights(const float* __restrict__ Wq_s, const float* __restrict__ Wk_s,
                             const float* __restrict__ Wv_s, const float* __restrict__ Wq_p,
                             const float* __restrict__ Wk_p, const float* __restrict__ Wv_p,
                             const float* __restrict__ bq_s, const float* __restrict__ bk_s,
                             const float* __restrict__ bv_s, const float* __restrict__ bq_p,
                             const float* __restrict__ bk_p, const float* __restrict__ bv_p,
                             const float* __restrict__ Wo, const float* __restrict__ pw,
                             const unsigned char* __restrict__ msk) {
    if (blockIdx.x == 0) {
        __shared__ int flag;
        int t = threadIdx.x;             // 256
        if (t == 0) flag = 0;
        __syncthreads();
        #pragma unroll
        for (int b = t; b < 512; b += 256)
            if ((b & 3) != 0 && msk[b] != 0) atomicOr(&flag, 1);
        __syncthreads();
        for (int i = t; i < SS; i += 256)
            g_maskf[i] = flag ? (msk[i] != 0 ? 1.0f : 0.0f)
                              : (((const int*)msk)[i] != 0 ? 1.0f : 0.0f);
        if (t < HH * 4) {
            float x = pw[t];
            g_spw[t] = (x > 20.0f) ? x : log1pf(expf(x));
        }
    }
    const int TOT  = CC * NPROJ;         // 442368
    const int TOTB = TOT + NPROJ;        // + bias
    const int TOTO = TOTB + COMB * CC;   // + Wo split
    for (int idx = blockIdx.x * blockDim.x + threadIdx.x; idx < TOTO;
         idx += gridDim.x * blockDim.x) {
        if (idx < TOT) {
            int k = idx / NPROJ, n = idx % NPROJ;
            float v;
            if      (n < 192)  v = Wq_s[k * 192 + n];
            else if (n < 384)  v = Wk_s[k * 192 + (n - 192)];
            else if (n < 576)  v = Wv_s[k * 192 + (n - 384)];
            else if (n < 720)  v = Wq_p[k * 144 + (n - 576)];
            else if (n < 864)  v = Wk_p[k * 144 + (n - 720)];
            else               v = Wv_p[k * 288 + (n - 864)];
            float hi = wmma::__float_to_tf32(v);
            g_Wh[idx] = hi;
            g_Wl[idx] = wmma::__float_to_tf32(v - hi);
        } else if (idx < TOTB) {
            int n = idx - TOT;
            float v;
            if      (n < 192)  v = bq_s[n];
            else if (n < 384)  v = bk_s[n - 192];
            else if (n < 576)  v = bv_s[n - 384];
            else if (n < 720)  v = bq_p[n - 576];
            else if (n < 864)  v = bk_p[n - 720];
            else               v = bv_p[n - 864];
            g_bc[n] = v;
        } else {
            int i = idx - TOTB;
            float v = Wo[i];
            float hi = wmma::__float_to_tf32(v);
            g_Woh[i] = hi;
            g_Wol[i] = wmma::__float_to_tf32(v - hi);
        }
    }
}

// ---------------- TF32x3 GEMM: C[M,N] = A@W + bias, row mask ---------------
// Block 64m x 64n, 256 threads = 8 warps (4m x 2n), warp = 16m x 32n.
// K chunked by 32. W pre-split (Wh/Wl tf32); A split on the fly.
__global__ void __launch_bounds__(256) gemm_tf32(
        const float* __restrict__ A, const float* __restrict__ Wh,
        const float* __restrict__ Wl, const float* __restrict__ bias,
        float* __restrict__ Cmat, int M, int N, int K,
        const float* __restrict__ mask) {
    // manual layout: sAh[64][40] | sAl[64][40] | sWh[32][72] | sWl[32][72]
    __shared__ __align__(16) float sm[9728];
    float* sAh = sm;                 // 2560
    float* sAl = sm + 2560;          // 2560
    float* sWh = sm + 5120;          // 2304
    float* sWl = sm + 7424;          // 2304
    float* stage = sm + 5120;        // 64x68 = 4352 floats (aliases sWh/sWl)

    int tid = threadIdx.x, wid = tid >> 5;
    int m0 = blockIdx.y * 64, n0 = blockIdx.x * 64;
    int wm = wid >> 1, wn = wid & 1;         // 4 x 2 warp grid

    wmma::fragment<wmma::accumulator, 16, 16, 8, float> fc[2];
    wmma::fill_fragment(fc[0], 0.0f);
    wmma::fill_fragment(fc[1], 0.0f);

    for (int k0 = 0; k0 < K; k0 += 32) {
        __syncthreads();
        // A chunk 64x32 -> tf32 hi/lo (coalesced reads)
        #pragma unroll
        for (int l = 0; l < 8; ++l) {
            int e = tid + l * 256;
            int r = e >> 5, c = e & 31;
            float v = A[(m0 + r) * K + k0 + c];
            float hi = wmma::__float_to_tf32(v);
            sAh[r * 40 + c] = hi;
            sAl[r * 40 + c] = wmma::__float_to_tf32(v - hi);
        }
        // W chunk 32x64 hi/lo (float4 copies)
        #pragma unroll
        for (int l = 0; l < 2; ++l) {
            int e = tid + l * 256;               // 512 float4 slots
            int r = e >> 4, c4 = e & 15;
            *(float4*)&sWh[r * 72 + c4 * 4] = *(const float4*)&Wh[(k0 + r) * N + n0 + c4 * 4];
            *(float4*)&sWl[r * 72 + c4 * 4] = *(const float4*)&Wl[(k0 + r) * N + n0 + c4 * 4];
        }
        __syncthreads();
        #pragma unroll
        for (int ks = 0; ks < 4; ++ks) {
            wmma::fragment<wmma::matrix_a, 16, 16, 8, wmma::precision::tf32, wmma::row_major> fah, fal;
            wmma::fragment<wmma::matrix_b, 16, 16, 8, wmma::precision::tf32, wmma::row_major> fbh[2], fbl[2];
            wmma::load_matrix_sync(fah, &sAh[(wm * 16) * 40 + ks * 8], 40);
            wmma::load_matrix_sync(fal, &sAl[(wm * 16) * 40 + ks * 8], 40);
            #pragma unroll
            for (int ni = 0; ni < 2; ++ni) {
                wmma::load_matrix_sync(fbh[ni], &sWh[(ks * 8) * 72 + wn * 32 + ni * 16], 72);
                wmma::load_matrix_sync(fbl[ni], &sWl[(ks * 8) * 72 + wn * 32 + ni * 16], 72);
            }
            #pragma unroll
            for (int ni = 0; ni < 2; ++ni) {
                wmma::mma_sync(fc[ni], fah, fbh[ni], fc[ni]);
                wmma::mma_sync(fc[ni], fah, fbl[ni], fc[ni]);
                wmma::mma_sync(fc[ni], fal, fbh[ni], fc[ni]);
            }
        }
    }
    __syncthreads();                               // before aliasing sWh as stage
    #pragma unroll
    for (int ni = 0; ni < 2; ++ni)
        wmma::store_matrix_sync(&stage[(wm * 16) * 68 + wn * 32 + ni * 16],
                                fc[ni], 68, wmma::mem_row_major);
    __syncthreads();
    // write out with bias + optional row mask (coalesced float4)
    #pragma unroll
    for (int l = 0; l < 4; ++l) {
        int e = tid + l * 256;                     // 1024 float4 slots (64x16)
        int r = e >> 4, c4 = e & 15;
        float sc = mask ? mask[m0 + r] : 1.0f;
        float4 b4 = *(const float4*)&bias[n0 + c4 * 4];
        float4 v;
        v.x = (stage[r * 68 + c4 * 4 + 0] + b4.x) * sc;
        v.y = (stage[r * 68 + c4 * 4 + 1] + b4.y) * sc;
        v.z = (stage[r * 68 + c4 * 4 + 2] + b4.z) * sc;
        v.w = (stage[r * 68 + c4 * 4 + 3] + b4.w) * sc;
        *(float4*)&Cmat[(m0 + r) * N + n0 + c4 * 4] = v;
    }
}

// ---------------- K2: rotate points, build augmented Q̃/K̃ (dim-major) + V --
__global__ void rotate_pack(const float* __restrict__ rot, const float* __restrict__ trans) {
    int s = blockIdx.x;
    int t = threadIdx.x;                 // 128 threads
    __shared__ float pts[576];
    __shared__ float Rs[9], ts_[3];
    if (t < 9) Rs[t] = rot[s * 9 + t];
    if (t >= 16 && t < 19) ts_[t - 16] = trans[s * 3 + (t - 16)];
    const float* pr = g_proj + s * NPROJ;

    #pragma unroll
    for (int e = t; e < 576; e += 128) {
        float v = pr[e];
        int seg = e / 192, r = e % 192;
        int h = r >> 4, d = r & 15;
        if      (seg == 0) g_Qa[h * (AD * SS) + d * SS + s] = 0.25f * v;
        else if (seg == 1) g_Ka[h * (AD * SS) + d * SS + s] = v;
        else               g_Vc[(h * SS + s) * VD + d] = v;
    }
    #pragma unroll
    for (int e = t; e < 576; e += 128) pts[e] = pr[576 + e];
    __syncthreads();

    if (t < 24) {
        bool isQ = t < 12;
        int h = isQ ? t : t - 12;
        const float* p = pts + (isQ ? 0 : 144) + h * 12;
        float* base = (isQ ? g_Qa : g_Ka) + h * (AD * SS);
        float s2 = 0.0f;
        #pragma unroll
        for (int pp = 0; pp < 4; ++pp) {
            float x = p[pp * 3 + 0], y = p[pp * 3 + 1], z = p[pp * 3 + 2];
            float gx = Rs[0] * x + Rs[1] * y + Rs[2] * z + ts_[0];
            float gy = Rs[3] * x + Rs[4] * y + Rs[5] * z + ts_[1];
            float gz = Rs[6] * x + Rs[7] * y + Rs[8] * z + ts_[2];
            float w = g_spw[h * 4 + pp];
            s2 += w * (gx * gx + gy * gy + gz * gz);
            float m = isQ ? w : 1.0f;
            base[(16 + pp * 3 + 0) * SS + s] = m * gx;
            base[(16 + pp * 3 + 1) * SS + s] = m * gy;
            base[(16 + pp * 3 + 2) * SS + s] = m * gz;
        }
        base[28 * SS + s] = isQ ? -0.5f * s2 : 1.0f;
        base[29 * SS + s] = isQ ? 1.0f : -0.5f * s2;
        base[30 * SS + s] = 0.0f;
        base[31 * SS + s] = 0.0f;
    } else if (t >= 32) {
        int q = t - 32;                   // 96 v-point tasks
        const float* p = pts + 288 + q * 3;
        float* o = g_Vc + ((q >> 3) * SS + s) * VD + 16 + (q & 7) * 3;
        float x = p[0], y = p[1], z = p[2];
        o[0] = Rs[0] * x + Rs[1] * y + Rs[2] * z + ts_[0];
        o[1] = Rs[3] * x + Rs[4] * y + Rs[5] * z + ts_[1];
        o[2] = Rs[6] * x + Rs[7] * y + Rs[8] * z + ts_[2];
    }
}

// ---------------- K3a: logits[h] = Q̃ᵀ K̃ ; tile 64m x 128n, 8x4 microtile --
__global__ void logits_gemm() {
    int h = blockIdx.z;
    int n0 = blockIdx.x * 128, m0 = blockIdx.y * 64;
    __shared__ __align__(16) float Qs[AD][64];
    __shared__ __align__(16) float Ks[AD][128];
    int tid = threadIdx.x;               // 256
    const float* qb = g_Qa + h * (AD * SS);
    const float* kb = g_Ka + h * (AD * SS);
    #pragma unroll
    for (int l = 0; l < 2; ++l) {
        int idx = tid + l * 256;
        int k = idx >> 4, m4 = idx & 15;
        *(float4*)&Qs[k][m4 * 4] = *(const float4*)&qb[k * SS + m0 + m4 * 4];
    }
    #pragma unroll
    for (int l = 0; l < 4; ++l) {
        int idx = tid + l * 256;
        int k = idx >> 5, n4 = idx & 31;
        *(float4*)&Ks[k][n4 * 4] = *(const float4*)&kb[k * SS + n0 + n4 * 4];
    }
    __syncthreads();
    int tx = tid & 31, ty = tid >> 5;
    float acc[8][4] = {};
    #pragma unroll
    for (int k = 0; k < AD; ++k) {
        float4 b4 = *(const float4*)&Ks[k][tx * 4];
        float4 a0 = *(const float4*)&Qs[k][ty * 8];
        float4 a1 = *(const float4*)&Qs[k][ty * 8 + 4];
        float av[8] = {a0.x, a0.y, a0.z, a0.w, a1.x, a1.y, a1.z, a1.w};
        float bv[4] = {b4.x, b4.y, b4.z, b4.w};
        #pragma unroll
        for (int i = 0; i < 8; ++i)
            #pragma unroll
            for (int j = 0; j < 4; ++j) acc[i][j] += av[i] * bv[j];
    }
    float4 mq = ((const float4*)g_maskf)[(n0 >> 2) + tx];
    #pragma unroll
    for (int i = 0; i < 8; ++i) {
        int m = m0 + ty * 8 + i;
        float4 v;
        v.x = (mq.x != 0.0f) ? acc[i][0] : -10000.0f;
        v.y = (mq.y != 0.0f) ? acc[i][1] : -10000.0f;
        v.z = (mq.z != 0.0f) ? acc[i][2] : -10000.0f;
        v.w = (mq.w != 0.0f) ? acc[i][3] : -10000.0f;
        *(float4*)&g_attn[(h * SS + m) * SS + n0 + tx * 4] = v;
    }
}

// ---------------- K3b: softmax over rows of g_attn (warp per row) ----------
__global__ void softmax_rows() {
    int row = blockIdx.x * 8 + (threadIdx.x >> 5);
    int lane = threadIdx.x & 31;
    float* r = g_attn + row * SS;
    float4 v[4];
    float m = -1e30f;
    #pragma unroll
    for (int c = 0; c < 4; ++c) {
        v[c] = *(const float4*)&r[(lane + c * 32) * 4];
        m = fmaxf(m, fmaxf(fmaxf(v[c].x, v[c].y), fmaxf(v[c].z, v[c].w)));
    }
    #pragma unroll
    for (int o = 16; o; o >>= 1) m = fmaxf(m, __shfl_xor_sync(0xFFFFFFFFu, m, o));
    float sum = 0.0f;
    #pragma unroll
    for (int c = 0; c < 4; ++c) {
        v[c].x = __expf(v[c].x - m);  v[c].y = __expf(v[c].y - m);
        v[c].z = __expf(v[c].z - m);  v[c].w = __expf(v[c].w - m);
        sum += v[c].x + v[c].y + v[c].z + v[c].w;
    }
    #pragma unroll
    for (int o = 16; o; o >>= 1) sum += __shfl_xor_sync(0xFFFFFFFFu, sum, o);
    float inv = g_maskf[row & (SS - 1)] / sum;
    #pragma unroll
    for (int c = 0; c < 4; ++c) {
        v[c].x *= inv;  v[c].y *= inv;  v[c].z *= inv;  v[c].w *= inv;
        *(float4*)&r[(lane + c * 32) * 4] = v[c];
    }
}

// ---------------- K4: attn@V fused with combined-feature epilogue ----------
__global__ void attn_apply(const float* __restrict__ rot, const float* __restrict__ trans) {
    int h = blockIdx.y, i0 = blockIdx.x * 32;
    __shared__ __align__(16) float at[32][68];
    __shared__ __align__(16) float vv[64][VD];
    __shared__ __align__(16) float ot[32][44];
    int tid = threadIdx.x;
    int il = tid >> 3, dg = tid & 7;
    float acc[5] = {};
    for (int j0 = 0; j0 < SS; j0 += 64) {
        #pragma unroll
        for (int l = 0; l < 2; ++l) {
            int idx = tid + l * 256;
            int rr = idx >> 4, c4 = idx & 15;
            *(float4*)&at[rr][c4 * 4] =
                *(const float4*)&g_attn[(h * SS + i0 + rr) * SS + j0 + c4 * 4];
        }
        #pragma unroll
        for (int l = 0; l < 3; ++l) {
            int idx = tid + l * 256;
            if (idx < 640) {
                int rr = idx / 10, c4 = idx % 10;
                *(float4*)&vv[rr][c4 * 4] =
                    ((const float4*)(g_Vc + (h * SS + j0 + rr) * VD))[c4];
            }
        }
        __syncthreads();
        #pragma unroll 8
        for (int jj = 0; jj < 64; ++jj) {
            float a = at[il][jj];
            #pragma unroll
            for (int q = 0; q < 5; ++q) acc[q] += a * vv[jj][dg * 5 + q];
        }
        __syncthreads();
    }
    #pragma unroll
    for (int q = 0; q < 5; ++q) ot[il][dg * 5 + q] = acc[q];
    __syncthreads();

    #pragma unroll
    for (int l = 0; l < 2; ++l) {
        int e = tid + l * 256;
        int q = e >> 4, d = e & 15;
        g_comb[(i0 + q) * COMB + h * 16 + d] = ot[q][d];
    }
    {
        int q = tid >> 3, p = tid & 7;
        int s = i0 + q;
        float v0 = ot[q][16 + 3 * p + 0] - trans[s * 3 + 0];
        float v1 = ot[q][16 + 3 * p + 1] - trans[s * 3 + 1];
        float v2 = ot[q][16 + 3 * p + 2] - trans[s * 3 + 2];
        const float* R = rot + s * 9;
        float p0 = R[0] * v0 + R[3] * v1 + R[6] * v2;
        float p1 = R[1] * v0 + R[4] * v1 + R[7] * v2;
        float p2 = R[2] * v0 + R[5] * v1 + R[8] * v2;
        float* cb = g_comb + s * COMB;
        cb[192 + (h * 8 + p) * 3 + 0] = p0;
        cb[192 + (h * 8 + p) * 3 + 1] = p1;
        cb[192 + (h * 8 + p) * 3 + 2] = p2;
        cb[480 + h * 8 + p] = sqrtf(p0 * p0 + p1 * p1 + p2 * p2);
    }
}

// ---------------------------------------------------------------------------
extern "C" void kernel_launch(void* const* d_in, const int* in_sizes, int n_in,
                              void* d_out, int out_size) {
    const float* single = (const float*)d_in[0];
    const float* rot    = (const float*)d_in[1];
    const float* trans  = (const float*)d_in[2];
    const float* Wq_s = (const float*)d_in[3];  const float* bq_s = (const float*)d_in[4];
    const float* Wk_s = (const float*)d_in[5];  const float* bk_s = (const float*)d_in[6];
    const float* Wv_s = (const float*)d_in[7];  const float* bv_s = (const float*)d_in[8];
    const float* Wq_p = (const float*)d_in[9];  const float* bq_p = (const float*)d_in[10];
    const float* Wk_p = (const float*)d_in[11]; const float* bk_p = (const float*)d_in[12];
    const float* Wv_p = (const float*)d_in[13]; const float* bv_p = (const float*)d_in[14];
    const float* pw   = (const float*)d_in[15];
    const float* Wo   = (const float*)d_in[16];
    const float* bo   = (const float*)d_in[17];
    const unsigned char* mask = (const unsigned char*)d_in[18];
    float* out = (float*)d_out;

    float *pWh, *pWl, *pWoh, *pWol, *pbc, *pproj, *pcomb, *pmaskf;
    cudaGetSymbolAddress((void**)&pWh,    g_Wh);
    cudaGetSymbolAddress((void**)&pWl,    g_Wl);
    cudaGetSymbolAddress((void**)&pWoh,   g_Woh);
    cudaGetSymbolAddress((void**)&pWol,   g_Wol);
    cudaGetSymbolAddress((void**)&pbc,    g_bc);
    cudaGetSymbolAddress((void**)&pproj,  g_proj);
    cudaGetSymbolAddress((void**)&pcomb,  g_comb);
    cudaGetSymbolAddress((void**)&pmaskf, g_maskf);

    pack_weights<<<432, 256>>>(Wq_s, Wk_s, Wv_s, Wq_p, Wk_p, Wv_p,
                               bq_s, bk_s, bv_s, bq_p, bk_p, bv_p, Wo, pw, mask);
    gemm_tf32<<<dim3(NPROJ / 64, SS / 64), 256>>>(single, pWh, pWl, pbc, pproj,
                                                  SS, NPROJ, CC, (const float*)0);
    rotate_pack<<<SS, 128>>>(rot, trans);
    logits_gemm<<<dim3(SS / 128, SS / 64, HH), 256>>>();
    softmax_rows<<<HH * SS / 8, 256>>>();
    attn_apply<<<dim3(SS / 32, HH), 256>>>(rot, trans);
    gemm_tf32<<<dim3(CC / 64, SS / 64), 256>>>(pcomb, pWoh, pWol, bo, out,
                                               SS, CC, COMB, pmaskf);
}

// round 12
// speedup vs baseline: 1.0565x; 1.0565x over previous
#include <cuda_runtime.h>
#include <math.h>

#define SS 512
#define CC 384
#define HH 12
#define NPROJ 1152   // 192 qs + 192 ks + 192 vs + 144 qp + 144 kp + 288 vp
#define AD 32        // augmented logit dim (30 used, padded to 32)
#define VD 40        // 16 scalar + 8 points * 3
#define COMB 576     // 192 scalar_out + 288 pol + 96 norms
#define LGS 516      // padded lg row stride

// ---------------- scratch (device globals; no allocation allowed) ----------
__device__ float g_Wc[CC * NPROJ];
__device__ float g_bc[NPROJ];
__device__ float g_proj[SS * NPROJ];
__device__ float g_Qa[HH * AD * SS];     // dim-major augmented Q
__device__ float g_Ka[HH * AD * SS];     // dim-major augmented K
__device__ float g_Vc[HH * SS * VD];
__device__ float g_comb[SS * COMB];
__device__ float g_maskf[SS];
__device__ float g_spw[HH * 4];          // softplus(point_weights)

// ---------------- K0: pack weights (float4 segment copies) + mask + softplus
__global__ void pack_weights(const float* __restrict__ Wq_s, const float* __restrict__ Wk_s,
                             const float* __restrict__ Wv_s, const float* __restrict__ Wq_p,
                             const float* __restrict__ Wk_p, const float* __restrict__ Wv_p,
                             const float* __restrict__ bq_s, const float* __restrict__ bk_s,
                             const float* __restrict__ bv_s, const float* __restrict__ bq_p,
                             const float* __restrict__ bk_p, const float* __restrict__ bv_p,
                             const float* __restrict__ pw,
                             const unsigned char* __restrict__ msk) {
    if (blockIdx.x == 0) {
        __shared__ int flag;
        int t = threadIdx.x;             // 256
        if (t == 0) flag = 0;
        __syncthreads();
        #pragma unroll
        for (int b = t; b < 512; b += 256)
            if ((b & 3) != 0 && msk[b] != 0) atomicOr(&flag, 1);
        __syncthreads();
        for (int i = t; i < SS; i += 256)
            g_maskf[i] = flag ? (msk[i] != 0 ? 1.0f : 0.0f)
                              : (((const int*)msk)[i] != 0 ? 1.0f : 0.0f);
        if (t < HH * 4) {
            float x = pw[t];
            g_spw[t] = (x > 20.0f) ? x : log1pf(expf(x));
        }
    }
    const int ROW4 = NPROJ / 4;          // 288
    const int TOT4 = CC * ROW4;          // 110592
    float4* dstW = (float4*)g_Wc;
    for (int idx = blockIdx.x * blockDim.x + threadIdx.x; idx < TOT4 + ROW4;
         idx += gridDim.x * blockDim.x) {
        if (idx < TOT4) {
            int row = idx / ROW4, r = idx % ROW4;
            const float* src;  int c4, w4;
            if      (r < 48)  { src = Wq_s; c4 = r;        w4 = 48; }
            else if (r < 96)  { src = Wk_s; c4 = r - 48;   w4 = 48; }
            else if (r < 144) { src = Wv_s; c4 = r - 96;   w4 = 48; }
            else if (r < 180) { src = Wq_p; c4 = r - 144;  w4 = 36; }
            else if (r < 216) { src = Wk_p; c4 = r - 180;  w4 = 36; }
            else              { src = Wv_p; c4 = r - 216;  w4 = 72; }
            dstW[idx] = ((const float4*)src)[row * w4 + c4];
        } else {
            int r = idx - TOT4;
            const float* src;  int c4;
            if      (r < 48)  { src = bq_s; c4 = r; }
            else if (r < 96)  { src = bk_s; c4 = r - 48; }
            else if (r < 144) { src = bv_s; c4 = r - 96; }
            else if (r < 180) { src = bq_p; c4 = r - 144; }
            else if (r < 216) { src = bk_p; c4 = r - 180; }
            else              { src = bv_p; c4 = r - 216; }
            ((float4*)g_bc)[r] = ((const float4*)src)[c4];
        }
    }
}

// ---------------- generic SGEMM (double-buffered, 256 thr, 4x4 microtile) --
__global__ void gemm64(const float* __restrict__ A, const float* __restrict__ W,
                       const float* __restrict__ bias, float* __restrict__ Cmat,
                       int M, int N, int K, const float* __restrict__ mask) {
    __shared__ __align__(16) float As[2][16][64];
    __shared__ __align__(16) float Ws[2][16][64];
    int tid = threadIdx.x;
    int tx = tid & 15, ty = tid >> 4;
    int n0 = blockIdx.x * 64, m0 = blockIdx.y * 64;

    int kkA[4], mA[4], nW[4], kkW[4];
    #pragma unroll
    for (int l = 0; l < 4; ++l) {
        int e = tid + l * 256;
        kkA[l] = e & 15;  mA[l] = e >> 4;
        nW[l]  = e & 63;  kkW[l] = e >> 6;
    }
    #pragma unroll
    for (int l = 0; l < 4; ++l) {
        As[0][kkA[l]][mA[l]] = A[(m0 + mA[l]) * K + kkA[l]];
        Ws[0][kkW[l]][nW[l]] = W[kkW[l] * N + n0 + nW[l]];
    }
    __syncthreads();

    float acc[4][4] = {};
    int nt = K >> 4;
    for (int t = 0; t < nt; ++t) {
        int cur = t & 1;
        float ar[4], wr[4];
        if (t + 1 < nt) {
            int k0n = (t + 1) << 4;
            #pragma unroll
            for (int l = 0; l < 4; ++l) {
                ar[l] = A[(m0 + mA[l]) * K + k0n + kkA[l]];
                wr[l] = W[(k0n + kkW[l]) * N + n0 + nW[l]];
            }
        }
        #pragma unroll
        for (int kk = 0; kk < 16; ++kk) {
            float4 a4 = *(const float4*)&As[cur][kk][ty * 4];
            float4 b4 = *(const float4*)&Ws[cur][kk][tx * 4];
            float av[4] = {a4.x, a4.y, a4.z, a4.w};
            float bv[4] = {b4.x, b4.y, b4.z, b4.w};
            #pragma unroll
            for (int i = 0; i < 4; ++i)
                #pragma unroll
                for (int j = 0; j < 4; ++j) acc[i][j] += av[i] * bv[j];
        }
        if (t + 1 < nt) {
            #pragma unroll
            for (int l = 0; l < 4; ++l) {
                As[cur ^ 1][kkA[l]][mA[l]] = ar[l];
                Ws[cur ^ 1][kkW[l]][nW[l]] = wr[l];
            }
        }
        __syncthreads();
    }
    #pragma unroll
    for (int i = 0; i < 4; ++i) {
        int m = m0 + ty * 4 + i;
        float sc = mask ? mask[m] : 1.0f;
        #pragma unroll
        for (int j = 0; j < 4; ++j) {
            int n = n0 + tx * 4 + j;
            Cmat[m * N + n] = (acc[i][j] + bias[n]) * sc;
        }
    }
}

// ---------------- K2: rotate points, build augmented Q̃/K̃ (dim-major) + V --
__global__ void rotate_pack(const float* __restrict__ rot, const float* __restrict__ trans) {
    int s = blockIdx.x;
    int t = threadIdx.x;                 // 128 threads
    __shared__ float pts[576];
    __shared__ float Rs[9], ts_[3];
    if (t < 9) Rs[t] = rot[s * 9 + t];
    if (t >= 16 && t < 19) ts_[t - 16] = trans[s * 3 + (t - 16)];
    const float* pr = g_proj + s * NPROJ;

    #pragma unroll
    for (int e = t; e < 576; e += 128) {
        float v = pr[e];
        int seg = e / 192, r = e % 192;
        int h = r >> 4, d = r & 15;
        if      (seg == 0) g_Qa[h * (AD * SS) + d * SS + s] = 0.25f * v;
        else if (seg == 1) g_Ka[h * (AD * SS) + d * SS + s] = v;
        else               g_Vc[(h * SS + s) * VD + d] = v;
    }
    #pragma unroll
    for (int e = t; e < 576; e += 128) pts[e] = pr[576 + e];
    __syncthreads();

    if (t < 24) {
        bool isQ = t < 12;
        int h = isQ ? t : t - 12;
        const float* p = pts + (isQ ? 0 : 144) + h * 12;
        float* base = (isQ ? g_Qa : g_Ka) + h * (AD * SS);
        float s2 = 0.0f;
        #pragma unroll
        for (int pp = 0; pp < 4; ++pp) {
            float x = p[pp * 3 + 0], y = p[pp * 3 + 1], z = p[pp * 3 + 2];
            float gx = Rs[0] * x + Rs[1] * y + Rs[2] * z + ts_[0];
            float gy = Rs[3] * x + Rs[4] * y + Rs[5] * z + ts_[1];
            float gz = Rs[6] * x + Rs[7] * y + Rs[8] * z + ts_[2];
            float w = g_spw[h * 4 + pp];
            s2 += w * (gx * gx + gy * gy + gz * gz);
            float m = isQ ? w : 1.0f;
            base[(16 + pp * 3 + 0) * SS + s] = m * gx;
            base[(16 + pp * 3 + 1) * SS + s] = m * gy;
            base[(16 + pp * 3 + 2) * SS + s] = m * gz;
        }
        base[28 * SS + s] = isQ ? -0.5f * s2 : 1.0f;
        base[29 * SS + s] = isQ ? 1.0f : -0.5f * s2;
        base[30 * SS + s] = 0.0f;
        base[31 * SS + s] = 0.0f;
    } else if (t >= 32) {
        int q = t - 32;                   // 96 v-point tasks
        const float* p = pts + 288 + q * 3;
        float* o = g_Vc + ((q >> 3) * SS + s) * VD + 16 + (q & 7) * 3;
        float x = p[0], y = p[1], z = p[2];
        o[0] = Rs[0] * x + Rs[1] * y + Rs[2] * z + ts_[0];
        o[1] = Rs[3] * x + Rs[4] * y + Rs[5] * z + ts_[1];
        o[2] = Rs[6] * x + Rs[7] * y + Rs[8] * z + ts_[2];
    }
}

// ---------------- K3: fused attention, 16-query tile ------------------------
// Block = (16 queries, head), 256 threads, grid 32x12 = 384 blocks.
// smem: lg[16][LGS] 33024B | Qs[32][16] 2048B | kv 20480B | ot 2816B = 58368B
__global__ void __launch_bounds__(256) attn_fused16(
        const float* __restrict__ rot, const float* __restrict__ trans) {
    extern __shared__ __align__(16) float sm[];
    float* lg = sm;                          // 16 * LGS
    float* Qs = lg + 16 * LGS;               // 32 x 16  (Qs[d*16+q])
    float* kv = Qs + 512;                    // Ks[32][128] or V[128][40]
    float* ot = kv + 5120;                   // 16 x 44 staging

    int h = blockIdx.x & 15 ? 0 : 0;         // placeholder (avoid warning)
    h = blockIdx.y;
    int i0 = blockIdx.x * 16;
    int tid = threadIdx.x;                   // 256
    const float* qb = g_Qa + h * (AD * SS);
    const float* kb = g_Ka + h * (AD * SS);

    // Q block: Qs[d][q]
    #pragma unroll
    for (int l = 0; l < 2; ++l) {
        int idx = tid + l * 256;             // 512
        int d = idx >> 4, q = idx & 15;
        Qs[d * 16 + q] = qb[d * SS + i0 + q];
    }

    // ---- phase 1: logits, 4 chunks of 128 keys ----
    int tx = tid & 31, ty = tid >> 5;        // key-group / query-pair
    for (int c = 0; c < 4; ++c) {
        int j0 = c * 128;
        __syncthreads();                     // kv reuse + Qs ready (first iter)
        #pragma unroll
        for (int l = 0; l < 4; ++l) {
            int idx = tid + l * 256;         // 1024 float4 slots
            int d = idx >> 5, n4 = idx & 31;
            *(float4*)&kv[d * 128 + n4 * 4] = *(const float4*)&kb[d * SS + j0 + n4 * 4];
        }
        __syncthreads();
        float acc[2][4] = {};
        #pragma unroll
        for (int d = 0; d < AD; ++d) {
            float4 k4 = *(const float4*)&kv[d * 128 + tx * 4];
            float q0 = Qs[d * 16 + ty * 2], q1 = Qs[d * 16 + ty * 2 + 1];
            acc[0][0] += q0 * k4.x;  acc[0][1] += q0 * k4.y;
            acc[0][2] += q0 * k4.z;  acc[0][3] += q0 * k4.w;
            acc[1][0] += q1 * k4.x;  acc[1][1] += q1 * k4.y;
            acc[1][2] += q1 * k4.z;  acc[1][3] += q1 * k4.w;
        }
        float4 mq = ((const float4*)g_maskf)[(j0 >> 2) + tx];
        #pragma unroll
        for (int i = 0; i < 2; ++i) {
            float4 v;
            v.x = (mq.x != 0.0f) ? acc[i][0] : -10000.0f;
            v.y = (mq.y != 0.0f) ? acc[i][1] : -10000.0f;
            v.z = (mq.z != 0.0f) ? acc[i][2] : -10000.0f;
            v.w = (mq.w != 0.0f) ? acc[i][3] : -10000.0f;
            *(float4*)&lg[(ty * 2 + i) * LGS + j0 + tx * 4] = v;
        }
    }
    __syncthreads();

    // ---- phase 2: softmax (8 warps x 2 rows) ----
    int lane = tid & 31, w = tid >> 5;
    #pragma unroll
    for (int rr = 0; rr < 2; ++rr) {
        int row = w * 2 + rr;
        float* r = lg + row * LGS;
        float m = -1e30f;
        #pragma unroll
        for (int c = 0; c < 16; ++c) m = fmaxf(m, r[lane + c * 32]);
        #pragma unroll
        for (int o = 16; o; o >>= 1) m = fmaxf(m, __shfl_xor_sync(0xFFFFFFFFu, m, o));
        float sum = 0.0f;
        #pragma unroll
        for (int c = 0; c < 16; ++c) {
            float e = __expf(r[lane + c * 32] - m);
            r[lane + c * 32] = e;
            sum += e;
        }
        #pragma unroll
        for (int o = 16; o; o >>= 1) sum += __shfl_xor_sync(0xFFFFFFFFu, sum, o);
        float inv = g_maskf[i0 + row] / sum;
        #pragma unroll
        for (int c = 0; c < 16; ++c) r[lane + c * 32] *= inv;
    }

    // ---- phase 3: P @ V, 4 chunks of 128 keys ----
    int il = tid >> 4;                       // query 0..15
    int sub = (tid >> 3) & 1;                // key half
    int dg = tid & 7;                        // 5-dim group
    float acc[5] = {};
    for (int j0 = 0; j0 < SS; j0 += 128) {
        __syncthreads();                     // protect kv (Ks in phase1 / prev V)
        #pragma unroll
        for (int l = 0; l < 5; ++l) {
            int idx = tid + l * 256;         // 1280 float4 slots
            int rr = idx / 10, c4 = idx % 10;
            *(float4*)&kv[rr * VD + c4 * 4] =
                ((const float4*)(g_Vc + (h * SS + j0 + rr) * VD))[c4];
        }
        __syncthreads();
        const float* lrow = lg + il * LGS + j0 + sub * 64;
        const float* vb = kv + sub * 64 * VD;
        #pragma unroll 8
        for (int jj = 0; jj < 64; ++jj) {
            float a = lrow[jj];
            #pragma unroll
            for (int q = 0; q < 5; ++q) acc[q] += a * vb[jj * VD + dg * 5 + q];
        }
    }
    __syncthreads();
    // combine halves via kv staging: part[q][sub][40]
    #pragma unroll
    for (int q = 0; q < 5; ++q) kv[(il * 2 + sub) * VD + dg * 5 + q] = acc[q];
    __syncthreads();
    if (tid < 128) {                          // 16q x 8dg
        int q = tid >> 3, d = tid & 7;
        #pragma unroll
        for (int i = 0; i < 5; ++i)
            ot[q * 44 + d * 5 + i] = kv[(q * 2) * VD + d * 5 + i]
                                   + kv[(q * 2 + 1) * VD + d * 5 + i];
    }
    __syncthreads();

    // ---- epilogue: combined features ----
    {   // scalar copies: 16q x 16d = 256 tasks
        int q = tid >> 4, d = tid & 15;
        g_comb[(i0 + q) * COMB + h * 16 + d] = ot[q * 44 + d];
    }
    if (tid < 128) {                          // 16q x 8p point tasks
        int q = tid >> 3, p = tid & 7;
        int s = i0 + q;
        float v0 = ot[q * 44 + 16 + 3 * p + 0] - trans[s * 3 + 0];
        float v1 = ot[q * 44 + 16 + 3 * p + 1] - trans[s * 3 + 1];
        float v2 = ot[q * 44 + 16 + 3 * p + 2] - trans[s * 3 + 2];
        const float* R = rot + s * 9;
        float p0 = R[0] * v0 + R[3] * v1 + R[6] * v2;   // R^T v
        float p1 = R[1] * v0 + R[4] * v1 + R[7] * v2;
        float p2 = R[2] * v0 + R[5] * v1 + R[8] * v2;
        float* cb = g_comb + s * COMB;
        cb[192 + (h * 8 + p) * 3 + 0] = p0;
        cb[192 + (h * 8 + p) * 3 + 1] = p1;
        cb[192 + (h * 8 + p) * 3 + 2] = p2;
        cb[480 + h * 8 + p] = sqrtf(p0 * p0 + p1 * p1 + p2 * p2);
    }
}

// ---------------------------------------------------------------------------
extern "C" void kernel_launch(void* const* d_in, const int* in_sizes, int n_in,
                              void* d_out, int out_size) {
    const float* single = (const float*)d_in[0];
    const float* rot    = (const float*)d_in[1];
    const float* trans  = (const float*)d_in[2];
    const float* Wq_s = (const float*)d_in[3];  const float* bq_s = (const float*)d_in[4];
    const float* Wk_s = (const float*)d_in[5];  const float* bk_s = (const float*)d_in[6];
    const float* Wv_s = (const float*)d_in[7];  const float* bv_s = (const float*)d_in[8];
    const float* Wq_p = (const float*)d_in[9];  const float* bq_p = (const float*)d_in[10];
    const float* Wk_p = (const float*)d_in[11]; const float* bk_p = (const float*)d_in[12];
    const float* Wv_p = (const float*)d_in[13]; const float* bv_p = (const float*)d_in[14];
    const float* pw   = (const float*)d_in[15];
    const float* Wo   = (const float*)d_in[16];
    const float* bo   = (const float*)d_in[17];
    const unsigned char* mask = (const unsigned char*)d_in[18];
    float* out = (float*)d_out;

    float *pWc, *pbc, *pproj, *pcomb, *pmaskf;
    cudaGetSymbolAddress((void**)&pWc,    g_Wc);
    cudaGetSymbolAddress((void**)&pbc,    g_bc);
    cudaGetSymbolAddress((void**)&pproj,  g_proj);
    cudaGetSymbolAddress((void**)&pcomb,  g_comb);
    cudaGetSymbolAddress((void**)&pmaskf, g_maskf);

    const int FUSED_SMEM = (16 * LGS + 512 + 5120 + 16 * 44) * 4;   // 58368 B
    cudaFuncSetAttribute(attn_fused16, cudaFuncAttributeMaxDynamicSharedMemorySize,
                         FUSED_SMEM);

    pack_weights<<<432, 256>>>(Wq_s, Wk_s, Wv_s, Wq_p, Wk_p, Wv_p,
                               bq_s, bk_s, bv_s, bq_p, bk_p, bv_p, pw, mask);
    gemm64<<<dim3(NPROJ / 64, SS / 64), 256>>>(single, pWc, pbc, pproj,
                                               SS, NPROJ, CC, (const float*)0);
    rotate_pack<<<SS, 128>>>(rot, trans);
    attn_fused16<<<dim3(SS / 16, HH), 256, FUSED_SMEM>>>(rot, trans);
    gemm64<<<dim3(CC / 64, SS / 64), 256>>>(pcomb, Wo, bo, out, SS, CC, COMB, pmaskf);
}

// round 13
// speedup vs baseline: 1.1950x; 1.1311x over previous
#include <cuda_runtime.h>
#include <math.h>

#define SS 512
#define CC 384
#define HH 12
#define NPROJ 1152   // 192 qs + 192 ks + 192 vs + 144 qp + 144 kp + 288 vp
#define AD 32        // augmented logit dim (30 used, padded to 32)
#define VD 40        // 16 scalar + 8 points * 3
#define COMB 576     // 192 scalar_out + 288 pol + 96 norms

// ---------------- scratch (device globals; no allocation allowed) ----------
__device__ float g_proj[SS * NPROJ];
__device__ float g_Qa[HH * AD * SS];     // dim-major augmented Q
__device__ float g_Ka[HH * AD * SS];     // dim-major augmented K
__device__ float g_Vc[HH * SS * VD];
__device__ float g_attn[HH * SS * SS];   // raw logits (key-masked)
__device__ float g_comb[SS * COMB];
__device__ float g_maskf[SS];

// ---------------- weight/bias column mapping (packed order) ----------------
__device__ __forceinline__ const float* wsrc(int n, int& w,
        const float* Wq_s, const float* Wk_s, const float* Wv_s,
        const float* Wq_p, const float* Wk_p, const float* Wv_p) {
    if (n < 576) {
        w = 192;
        if (n < 192) return Wq_s + n;
        if (n < 384) return Wk_s + (n - 192);
        return Wv_s + (n - 384);
    }
    if (n < 864) {
        w = 144;
        return (n < 720) ? (Wq_p + (n - 576)) : (Wk_p + (n - 720));
    }
    w = 288;
    return Wv_p + (n - 864);
}
__device__ __forceinline__ float bsrc(int n,
        const float* bq_s, const float* bk_s, const float* bv_s,
        const float* bq_p, const float* bk_p, const float* bv_p) {
    if (n < 192)  return bq_s[n];
    if (n < 384)  return bk_s[n - 192];
    if (n < 576)  return bv_s[n - 384];
    if (n < 720)  return bq_p[n - 576];
    if (n < 864)  return bk_p[n - 720];
    return bv_p[n - 864];
}

// ---------------- K1: projection GEMM, reads weight sources directly -------
// C[SS,NPROJ] = A[SS,CC] @ Wpacked + bias. 64x64 tile, 256 thr, double-buffered.
__global__ void gemm_proj(const float* __restrict__ A, float* __restrict__ Cmat,
        const float* __restrict__ Wq_s, const float* __restrict__ Wk_s,
        const float* __restrict__ Wv_s, const float* __restrict__ Wq_p,
        const float* __restrict__ Wk_p, const float* __restrict__ Wv_p,
        const float* __restrict__ bq_s, const float* __restrict__ bk_s,
        const float* __restrict__ bv_s, const float* __restrict__ bq_p,
        const float* __restrict__ bk_p, const float* __restrict__ bv_p) {
    const int K = CC, N = NPROJ;
    __shared__ __align__(16) float As[2][16][64];
    __shared__ __align__(16) float Ws[2][16][64];
    int tid = threadIdx.x;
    int tx = tid & 15, ty = tid >> 4;
    int n0 = blockIdx.x * 64, m0 = blockIdx.y * 64;

    int kkA[4], mA[4], nW[4], kkW[4];
    const float* bW[4];  int wstr[4];
    #pragma unroll
    for (int l = 0; l < 4; ++l) {
        int e = tid + l * 256;
        kkA[l] = e & 15;  mA[l] = e >> 4;
        nW[l]  = e & 63;  kkW[l] = e >> 6;
        bW[l] = wsrc(n0 + nW[l], wstr[l], Wq_s, Wk_s, Wv_s, Wq_p, Wk_p, Wv_p);
    }
    #pragma unroll
    for (int l = 0; l < 4; ++l) {
        As[0][kkA[l]][mA[l]] = A[(m0 + mA[l]) * K + kkA[l]];
        Ws[0][kkW[l]][nW[l]] = bW[l][kkW[l] * wstr[l]];
    }
    __syncthreads();

    float acc[4][4] = {};
    int nt = K >> 4;
    for (int t = 0; t < nt; ++t) {
        int cur = t & 1;
        float ar[4], wr[4];
        if (t + 1 < nt) {
            int k0n = (t + 1) << 4;
            #pragma unroll
            for (int l = 0; l < 4; ++l) {
                ar[l] = A[(m0 + mA[l]) * K + k0n + kkA[l]];
                wr[l] = bW[l][(k0n + kkW[l]) * wstr[l]];
            }
        }
        #pragma unroll
        for (int kk = 0; kk < 16; ++kk) {
            float4 a4 = *(const float4*)&As[cur][kk][ty * 4];
            float4 b4 = *(const float4*)&Ws[cur][kk][tx * 4];
            float av[4] = {a4.x, a4.y, a4.z, a4.w};
            float bv[4] = {b4.x, b4.y, b4.z, b4.w};
            #pragma unroll
            for (int i = 0; i < 4; ++i)
                #pragma unroll
                for (int j = 0; j < 4; ++j) acc[i][j] += av[i] * bv[j];
        }
        if (t + 1 < nt) {
            #pragma unroll
            for (int l = 0; l < 4; ++l) {
                As[cur ^ 1][kkA[l]][mA[l]] = ar[l];
                Ws[cur ^ 1][kkW[l]][nW[l]] = wr[l];
            }
        }
        __syncthreads();
    }
    float bj[4];
    #pragma unroll
    for (int j = 0; j < 4; ++j)
        bj[j] = bsrc(n0 + tx * 4 + j, bq_s, bk_s, bv_s, bq_p, bk_p, bv_p);
    #pragma unroll
    for (int i = 0; i < 4; ++i) {
        int m = m0 + ty * 4 + i;
        #pragma unroll
        for (int j = 0; j < 4; ++j)
            Cmat[m * N + n0 + tx * 4 + j] = acc[i][j] + bj[j];
    }
}

// ---------------- generic SGEMM (double-buffered, 256 thr, 4x4 microtile) --
__global__ void gemm64(const float* __restrict__ A, const float* __restrict__ W,
                       const float* __restrict__ bias, float* __restrict__ Cmat,
                       int M, int N, int K, const float* __restrict__ mask) {
    __shared__ __align__(16) float As[2][16][64];
    __shared__ __align__(16) float Ws[2][16][64];
    int tid = threadIdx.x;
    int tx = tid & 15, ty = tid >> 4;
    int n0 = blockIdx.x * 64, m0 = blockIdx.y * 64;

    int kkA[4], mA[4], nW[4], kkW[4];
    #pragma unroll
    for (int l = 0; l < 4; ++l) {
        int e = tid + l * 256;
        kkA[l] = e & 15;  mA[l] = e >> 4;
        nW[l]  = e & 63;  kkW[l] = e >> 6;
    }
    #pragma unroll
    for (int l = 0; l < 4; ++l) {
        As[0][kkA[l]][mA[l]] = A[(m0 + mA[l]) * K + kkA[l]];
        Ws[0][kkW[l]][nW[l]] = W[kkW[l] * N + n0 + nW[l]];
    }
    __syncthreads();

    float acc[4][4] = {};
    int nt = K >> 4;
    for (int t = 0; t < nt; ++t) {
        int cur = t & 1;
        float ar[4], wr[4];
        if (t + 1 < nt) {
            int k0n = (t + 1) << 4;
            #pragma unroll
            for (int l = 0; l < 4; ++l) {
                ar[l] = A[(m0 + mA[l]) * K + k0n + kkA[l]];
                wr[l] = W[(k0n + kkW[l]) * N + n0 + nW[l]];
            }
        }
        #pragma unroll
        for (int kk = 0; kk < 16; ++kk) {
            float4 a4 = *(const float4*)&As[cur][kk][ty * 4];
            float4 b4 = *(const float4*)&Ws[cur][kk][tx * 4];
            float av[4] = {a4.x, a4.y, a4.z, a4.w};
            float bv[4] = {b4.x, b4.y, b4.z, b4.w};
            #pragma unroll
            for (int i = 0; i < 4; ++i)
                #pragma unroll
                for (int j = 0; j < 4; ++j) acc[i][j] += av[i] * bv[j];
        }
        if (t + 1 < nt) {
            #pragma unroll
            for (int l = 0; l < 4; ++l) {
                As[cur ^ 1][kkA[l]][mA[l]] = ar[l];
                Ws[cur ^ 1][kkW[l]][nW[l]] = wr[l];
            }
        }
        __syncthreads();
    }
    #pragma unroll
    for (int i = 0; i < 4; ++i) {
        int m = m0 + ty * 4 + i;
        float sc = mask ? mask[m] : 1.0f;
        #pragma unroll
        for (int j = 0; j < 4; ++j) {
            int n = n0 + tx * 4 + j;
            Cmat[m * N + n] = (acc[i][j] + bias[n]) * sc;
        }
    }
}

// ---------------- K2: rotate + pack; block 0 canonicalizes mask ------------
__global__ void rotate_pack(const float* __restrict__ rot, const float* __restrict__ trans,
                            const float* __restrict__ pw,
                            const unsigned char* __restrict__ msk) {
    int s = blockIdx.x;
    int t = threadIdx.x;                 // 128 threads
    __shared__ float pts[576];
    __shared__ float Rs[9], ts_[3], spw_s[48];
    __shared__ int flag;

    if (blockIdx.x == 0) {               // mask dtype detect + canonicalize
        if (t == 0) flag = 0;
        __syncthreads();
        for (int b = t; b < 512; b += 128)
            if ((b & 3) != 0 && msk[b] != 0) atomicOr(&flag, 1);
        __syncthreads();
        for (int i = t; i < SS; i += 128)
            g_maskf[i] = flag ? (msk[i] != 0 ? 1.0f : 0.0f)
                              : (((const int*)msk)[i] != 0 ? 1.0f : 0.0f);
    }
    if (t < 9) Rs[t] = rot[s * 9 + t];
    if (t >= 16 && t < 19) ts_[t - 16] = trans[s * 3 + (t - 16)];
    if (t >= 64 && t < 112) {            // softplus(point_weights), per block
        float x = pw[t - 64];
        spw_s[t - 64] = (x > 20.0f) ? x : log1pf(expf(x));
    }
    const float* pr = g_proj + s * NPROJ;

    #pragma unroll
    for (int e = t; e < 576; e += 128) {
        float v = pr[e];
        int seg = e / 192, r = e % 192;
        int h = r >> 4, d = r & 15;
        if      (seg == 0) g_Qa[h * (AD * SS) + d * SS + s] = 0.25f * v;
        else if (seg == 1) g_Ka[h * (AD * SS) + d * SS + s] = v;
        else               g_Vc[(h * SS + s) * VD + d] = v;
    }
    #pragma unroll
    for (int e = t; e < 576; e += 128) pts[e] = pr[576 + e];
    __syncthreads();

    if (t < 24) {
        bool isQ = t < 12;
        int h = isQ ? t : t - 12;
        const float* p = pts + (isQ ? 0 : 144) + h * 12;
        float* base = (isQ ? g_Qa : g_Ka) + h * (AD * SS);
        float s2 = 0.0f;
        #pragma unroll
        for (int pp = 0; pp < 4; ++pp) {
            float x = p[pp * 3 + 0], y = p[pp * 3 + 1], z = p[pp * 3 + 2];
            float gx = Rs[0] * x + Rs[1] * y + Rs[2] * z + ts_[0];
            float gy = Rs[3] * x + Rs[4] * y + Rs[5] * z + ts_[1];
            float gz = Rs[6] * x + Rs[7] * y + Rs[8] * z + ts_[2];
            float w = spw_s[h * 4 + pp];
            s2 += w * (gx * gx + gy * gy + gz * gz);
            float m = isQ ? w : 1.0f;
            base[(16 + pp * 3 + 0) * SS + s] = m * gx;
            base[(16 + pp * 3 + 1) * SS + s] = m * gy;
            base[(16 + pp * 3 + 2) * SS + s] = m * gz;
        }
        base[28 * SS + s] = isQ ? -0.5f * s2 : 1.0f;
        base[29 * SS + s] = isQ ? 1.0f : -0.5f * s2;
        base[30 * SS + s] = 0.0f;
        base[31 * SS + s] = 0.0f;
    } else if (t >= 32) {
        int q = t - 32;                   // 96 v-point tasks
        const float* p = pts + 288 + q * 3;
        float* o = g_Vc + ((q >> 3) * SS + s) * VD + 16 + (q & 7) * 3;
        float x = p[0], y = p[1], z = p[2];
        o[0] = Rs[0] * x + Rs[1] * y + Rs[2] * z + ts_[0];
        o[1] = Rs[3] * x + Rs[4] * y + Rs[5] * z + ts_[1];
        o[2] = Rs[6] * x + Rs[7] * y + Rs[8] * z + ts_[2];
    }
}

// ---------------- K3: raw logits[h] = Q̃ᵀ K̃ (key mask applied) -------------
__global__ void logits_gemm() {
    int h = blockIdx.z;
    int n0 = blockIdx.x * 128, m0 = blockIdx.y * 64;
    __shared__ __align__(16) float Qs[AD][64];
    __shared__ __align__(16) float Ks[AD][128];
    int tid = threadIdx.x;               // 256
    const float* qb = g_Qa + h * (AD * SS);
    const float* kb = g_Ka + h * (AD * SS);
    #pragma unroll
    for (int l = 0; l < 2; ++l) {
        int idx = tid + l * 256;
        int k = idx >> 4, m4 = idx & 15;
        *(float4*)&Qs[k][m4 * 4] = *(const float4*)&qb[k * SS + m0 + m4 * 4];
    }
    #pragma unroll
    for (int l = 0; l < 4; ++l) {
        int idx = tid + l * 256;
        int k = idx >> 5, n4 = idx & 31;
        *(float4*)&Ks[k][n4 * 4] = *(const float4*)&kb[k * SS + n0 + n4 * 4];
    }
    __syncthreads();
    int tx = tid & 31, ty = tid >> 5;
    float acc[8][4] = {};
    #pragma unroll
    for (int k = 0; k < AD; ++k) {
        float4 b4 = *(const float4*)&Ks[k][tx * 4];
        float4 a0 = *(const float4*)&Qs[k][ty * 8];
        float4 a1 = *(const float4*)&Qs[k][ty * 8 + 4];
        float av[8] = {a0.x, a0.y, a0.z, a0.w, a1.x, a1.y, a1.z, a1.w};
        float bv[4] = {b4.x, b4.y, b4.z, b4.w};
        #pragma unroll
        for (int i = 0; i < 8; ++i)
            #pragma unroll
            for (int j = 0; j < 4; ++j) acc[i][j] += av[i] * bv[j];
    }
    float4 mq = ((const float4*)g_maskf)[(n0 >> 2) + tx];
    #pragma unroll
    for (int i = 0; i < 8; ++i) {
        int m = m0 + ty * 8 + i;
        float4 v;
        v.x = (mq.x != 0.0f) ? acc[i][0] : -10000.0f;
        v.y = (mq.y != 0.0f) ? acc[i][1] : -10000.0f;
        v.z = (mq.z != 0.0f) ? acc[i][2] : -10000.0f;
        v.w = (mq.w != 0.0f) ? acc[i][3] : -10000.0f;
        *(float4*)&g_attn[(h * SS + m) * SS + n0 + tx * 4] = v;
    }
}

// ---------------- K4: softmax-inline attn@V + combined epilogue ------------
__global__ void attn_apply(const float* __restrict__ rot, const float* __restrict__ trans) {
    int h = blockIdx.y, i0 = blockIdx.x * 32;
    __shared__ __align__(16) float at[32][68];
    __shared__ __align__(16) float vv[64][VD];
    __shared__ __align__(16) float ot[32][44];
    __shared__ float mx[32], inv_s[32];
    int tid = threadIdx.x;
    int w = tid >> 5, lane = tid & 31;

    // phase 0: per-row max + sum(exp) over raw logits (warp per 4 rows)
    #pragma unroll
    for (int rr = 0; rr < 4; ++rr) {
        int r = w * 4 + rr;
        const float4* row = (const float4*)(g_attn + (h * SS + i0 + r) * SS);
        float4 v[4];
        float m = -1e30f;
        #pragma unroll
        for (int c = 0; c < 4; ++c) {
            v[c] = row[lane + c * 32];
            m = fmaxf(m, fmaxf(fmaxf(v[c].x, v[c].y), fmaxf(v[c].z, v[c].w)));
        }
        #pragma unroll
        for (int o = 16; o; o >>= 1) m = fmaxf(m, __shfl_xor_sync(0xFFFFFFFFu, m, o));
        float sum = 0.0f;
        #pragma unroll
        for (int c = 0; c < 4; ++c)
            sum += __expf(v[c].x - m) + __expf(v[c].y - m)
                 + __expf(v[c].z - m) + __expf(v[c].w - m);
        #pragma unroll
        for (int o = 16; o; o >>= 1) sum += __shfl_xor_sync(0xFFFFFFFFu, sum, o);
        if (lane == 0) { mx[r] = m; inv_s[r] = g_maskf[i0 + r] / sum; }
    }
    __syncthreads();

    int il = tid >> 3, dg = tid & 7;   // 32 queries x 8 dim-groups (5 dims each)
    float acc[5] = {};
    for (int j0 = 0; j0 < SS; j0 += 64) {
        #pragma unroll
        for (int l = 0; l < 2; ++l) {            // 512 float4 fills of at
            int idx = tid + l * 256;
            int rr = idx >> 4, c4 = idx & 15;
            float4 g = *(const float4*)&g_attn[(h * SS + i0 + rr) * SS + j0 + c4 * 4];
            float m = mx[rr], iv = inv_s[rr];
            float4 e;
            e.x = __expf(g.x - m) * iv;  e.y = __expf(g.y - m) * iv;
            e.z = __expf(g.z - m) * iv;  e.w = __expf(g.w - m) * iv;
            *(float4*)&at[rr][c4 * 4] = e;
        }
        #pragma unroll
        for (int l = 0; l < 3; ++l) {            // 640 float4 fills of vv
            int idx = tid + l * 256;
            if (idx < 640) {
                int rr = idx / 10, c4 = idx % 10;
                *(float4*)&vv[rr][c4 * 4] =
                    ((const float4*)(g_Vc + (h * SS + j0 + rr) * VD))[c4];
            }
        }
        __syncthreads();
        #pragma unroll 8
        for (int jj = 0; jj < 64; ++jj) {
            float a = at[il][jj];
            #pragma unroll
            for (int q = 0; q < 5; ++q) acc[q] += a * vv[jj][dg * 5 + q];
        }
        __syncthreads();
    }
    #pragma unroll
    for (int q = 0; q < 5; ++q) ot[il][dg * 5 + q] = acc[q];
    __syncthreads();

    // epilogue: scalar copies (512 tasks -> 2 per thread)
    #pragma unroll
    for (int l = 0; l < 2; ++l) {
        int e = tid + l * 256;
        int q = e >> 4, d = e & 15;
        g_comb[(i0 + q) * COMB + h * 16 + d] = ot[q][d];
    }
    // epilogue: point tasks (32 queries x 8 points = 256)
    {
        int q = tid >> 3, p = tid & 7;
        int s = i0 + q;
        float v0 = ot[q][16 + 3 * p + 0] - trans[s * 3 + 0];
        float v1 = ot[q][16 + 3 * p + 1] - trans[s * 3 + 1];
        float v2 = ot[q][16 + 3 * p + 2] - trans[s * 3 + 2];
        const float* R = rot + s * 9;
        float p0 = R[0] * v0 + R[3] * v1 + R[6] * v2;   // R^T v
        float p1 = R[1] * v0 + R[4] * v1 + R[7] * v2;
        float p2 = R[2] * v0 + R[5] * v1 + R[8] * v2;
        float* cb = g_comb + s * COMB;
        cb[192 + (h * 8 + p) * 3 + 0] = p0;
        cb[192 + (h * 8 + p) * 3 + 1] = p1;
        cb[192 + (h * 8 + p) * 3 + 2] = p2;
        cb[480 + h * 8 + p] = sqrtf(p0 * p0 + p1 * p1 + p2 * p2);
    }
}

// ---------------------------------------------------------------------------
extern "C" void kernel_launch(void* const* d_in, const int* in_sizes, int n_in,
                              void* d_out, int out_size) {
    const float* single = (const float*)d_in[0];
    const float* rot    = (const float*)d_in[1];
    const float* trans  = (const float*)d_in[2];
    const float* Wq_s = (const float*)d_in[3];  const float* bq_s = (const float*)d_in[4];
    const float* Wk_s = (const float*)d_in[5];  const float* bk_s = (const float*)d_in[6];
    const float* Wv_s = (const float*)d_in[7];  const float* bv_s = (const float*)d_in[8];
    const float* Wq_p = (const float*)d_in[9];  const float* bq_p = (const float*)d_in[10];
    const float* Wk_p = (const float*)d_in[11]; const float* bk_p = (const float*)d_in[12];
    const float* Wv_p = (const float*)d_in[13]; const float* bv_p = (const float*)d_in[14];
    const float* pw   = (const float*)d_in[15];
    const float* Wo   = (const float*)d_in[16];
    const float* bo   = (const float*)d_in[17];
    const unsigned char* mask = (const unsigned char*)d_in[18];
    float* out = (float*)d_out;

    float *pproj, *pcomb, *pmaskf;
    cudaGetSymbolAddress((void**)&pproj,  g_proj);
    cudaGetSymbolAddress((void**)&pcomb,  g_comb);
    cudaGetSymbolAddress((void**)&pmaskf, g_maskf);

    gemm_proj<<<dim3(NPROJ / 64, SS / 64), 256>>>(single, pproj,
        Wq_s, Wk_s, Wv_s, Wq_p, Wk_p, Wv_p,
        bq_s, bk_s, bv_s, bq_p, bk_p, bv_p);
    rotate_pack<<<SS, 128>>>(rot, trans, pw, mask);
    logits_gemm<<<dim3(SS / 128, SS / 64, HH), 256>>>();
    attn_apply<<<dim3(SS / 32, HH), 256>>>(rot, trans);
    gemm64<<<dim3(CC / 64, SS / 64), 256>>>(pcomb, Wo, bo, out, SS, CC, COMB, pmaskf);
}